// round 6
// baseline (speedup 1.0000x reference)
#include <cuda_runtime.h>
#include <cuda_bf16.h>
#include <math.h>

#define NN 2048
#define BB 32
#define NSTEPS 10
#define KSPLIT 8
#define KC 256                // K chunk per CTA
#define MT 128                // rows per CTA
#define CTAS 128
#define THREADS 256
#define SSTR 264              // smem row stride (bf16 elems)
#define SA_ELEMS (MT * SSTR)
#define SB_ELEMS (64 * SSTR)
#define SMEM_BYTES ((SA_ELEMS + SB_ELEMS) * 2)
#define NLEAF 8
#define LEAF_SZ (CTAS / NLEAF)    // 16

// Persistent scratch (no allocations allowed)
__device__ __align__(16) __nv_bfloat16 g_SCb[64 * NN];   // rows 0-31 sin, 32-63 cos
__device__ __align__(16) float g_ps[KSPLIT][BB * NN];    // partial K*sin  [b*NN+i]
__device__ __align__(16) float g_pc[KSPLIT][BB * NN];    // partial K*cos
__device__ __align__(16) float2 g_cohP[CTAS];
__device__ __align__(16) float g_theta_fallback[BB * NN];
// barrier state: leaves on distinct 128B lines, root + gen on own lines
__device__ __align__(128) unsigned g_leaf[NLEAF * 32];
__device__ __align__(128) unsigned g_root;
__device__ __align__(128) unsigned g_gen;

static __device__ __forceinline__ void cp16(void* dst_smem, const void* src) {
    unsigned d = (unsigned)__cvta_generic_to_shared(dst_smem);
    asm volatile("cp.async.cg.shared.global [%0], [%1], 16;\n" :: "r"(d), "l"(src));
}
static __device__ __forceinline__ void cp_commit() {
    asm volatile("cp.async.commit_group;\n");
}
static __device__ __forceinline__ void cp_wait0() {
    asm volatile("cp.async.wait_group 0;\n");
}

// Two-level sense-reversing grid barrier (128 co-resident CTAs).
// Arrivals: 8 leaf counters (parallel LTS slices) -> 1 root counter.
// Waiters poll with acquire LOADS (no RMW serialization).
static __device__ __forceinline__ void gbar(int bid) {
    __syncthreads();
    if (threadIdx.x == 0) {
        unsigned my;
        asm volatile("ld.acquire.gpu.global.u32 %0, [%1];"
                     : "=r"(my) : "l"(&g_gen) : "memory");
        __threadfence();                          // release this CTA's writes
        int leaf = bid >> 4;                      // 16 CTAs per leaf
        unsigned a = atomicAdd(&g_leaf[leaf * 32], 1u);
        if (a == LEAF_SZ - 1) {
            unsigned r = atomicAdd(&g_root, 1u);
            if (r == NLEAF - 1) {
                g_root = 0u;                      // reset before release
#pragma unroll
                for (int i = 0; i < NLEAF; i++) g_leaf[i * 32] = 0u;
                asm volatile("red.release.gpu.global.add.u32 [%0], %1;"
                             :: "l"(&g_gen), "r"(1u) : "memory");
            }
        }
        unsigned v;
        do {
            __nanosleep(32);
            asm volatile("ld.acquire.gpu.global.u32 %0, [%1];"
                         : "=r"(v) : "l"(&g_gen) : "memory");
        } while (v == my);
        __threadfence();                          // acquire for whole CTA
    }
    __syncthreads();
}

__global__ void __launch_bounds__(THREADS, 1)
k_all(const float* __restrict__ theta_in, const float* __restrict__ K,
      const float* __restrict__ omega, const float* __restrict__ Kg,
      const float* __restrict__ mu, float* __restrict__ th_out,
      float* __restrict__ coh_out) {
    extern __shared__ __align__(16) char smem_raw[];
    __nv_bfloat16* sA = (__nv_bfloat16*)smem_raw;        // K tile, resident all steps
    __nv_bfloat16* sB = sA + SA_ELEMS;                   // sin/cos tile, per step

    int tid  = threadIdx.x;
    int lane = tid & 31;
    int w    = tid >> 5;
    int bid  = blockIdx.x;
    int ib   = bid >> 3, ks = bid & 7;
    int i0   = ib * MT, k0 = ks * KC;
    int g    = lane >> 2, t = lane & 3;

    // ---- prologue 1: convert this CTA's fp32 K tile -> bf16 smem (once) ----
    {
        const float* Kt = K + (size_t)i0 * NN + k0;
#pragma unroll 4
        for (int it = 0; it < 32; it++) {
            int idx = it * THREADS + tid;           // 8192 float4 total
            int row = idx >> 6, c = idx & 63;
            float4 v = *(const float4*)(Kt + (size_t)row * NN + c * 4);
            __nv_bfloat162 lo = __floats2bfloat162_rn(v.x, v.y);
            __nv_bfloat162 hi = __floats2bfloat162_rn(v.z, v.w);
            uint2 pk = make_uint2(*(unsigned*)&lo, *(unsigned*)&hi);
            *(uint2*)(sA + row * SSTR + c * 4) = pk;
        }
    }

    // ---- prologue 2: per-thread theta state (2 elements, fixed mapping) ----
    int eidx = (bid * THREADS + tid) * 2;
    int igl  = eidx & (NN - 1);
    float th0 = theta_in[eidx], th1 = theta_in[eidx + 1];
    float om0 = omega[igl],     om1 = omega[igl + 1];
    float coef = (Kg[0] * (1.0f / NN)) * (mu[0] * 0.5f);
    float s0, c0, s1, c1;
    sincosf(th0, &s0, &c0);     // one-time accurate seed
    sincosf(th1, &s1, &c1);
    __nv_bfloat162 sb2 = __floats2bfloat162_rn(s0, s1);
    __nv_bfloat162 cb2 = __floats2bfloat162_rn(c0, c1);
    *(__nv_bfloat162*)&g_SCb[eidx]           = sb2;
    *(__nv_bfloat162*)&g_SCb[32 * NN + eidx] = cb2;
    float si0 = __low2float(sb2), si1 = __high2float(sb2);
    float ci0 = __low2float(cb2), ci1 = __high2float(cb2);

    gbar(bid);

    // ---- 10 steps: MMA phase + update phase ----
    for (int step = 0; step < NSTEPS; step++) {
        // fill B tile: 64 rows x 256 bf16 (sin rows 0-31, cos rows 32-63)
#pragma unroll
        for (int it = 0; it < 8; it++) {
            int idx = it * THREADS + tid;            // 2048 x 16B
            int row = idx >> 5, c = idx & 31;
            cp16(sB + row * SSTR + c * 8,
                 g_SCb + (size_t)row * NN + k0 + c * 8);
        }
        cp_commit();
        cp_wait0();
        __syncthreads();

        float acc[8][4];
#pragma unroll
        for (int nt = 0; nt < 8; nt++)
#pragma unroll
            for (int r = 0; r < 4; r++) acc[nt][r] = 0.f;

#pragma unroll 4
        for (int kk = 0; kk < KC; kk += 16) {
            unsigned a0, a1, a2, a3;
            const __nv_bfloat16* ap =
                sA + (w * 16 + (lane & 15)) * SSTR + kk + ((lane >> 4) * 8);
            unsigned sa = (unsigned)__cvta_generic_to_shared(ap);
            asm volatile(
                "ldmatrix.sync.aligned.m8n8.x4.shared.b16 {%0,%1,%2,%3}, [%4];"
                : "=r"(a0), "=r"(a1), "=r"(a2), "=r"(a3) : "r"(sa));
#pragma unroll
            for (int nt = 0; nt < 8; nt++) {
                const __nv_bfloat16* p = sB + (nt * 8 + g) * SSTR + kk + 2 * t;
                unsigned b0 = *(const unsigned*)p;
                unsigned b1 = *(const unsigned*)(p + 8);
                asm volatile(
                    "mma.sync.aligned.m16n8k16.row.col.f32.bf16.bf16.f32 "
                    "{%0,%1,%2,%3}, {%4,%5,%6,%7}, {%8,%9}, {%0,%1,%2,%3};"
                    : "+f"(acc[nt][0]), "+f"(acc[nt][1]),
                      "+f"(acc[nt][2]), "+f"(acc[nt][3])
                    : "r"(a0), "r"(a1), "r"(a2), "r"(a3), "r"(b0), "r"(b1));
            }
        }

        // store partials: cols 0-31 -> sin partials, 32-63 -> cos
        {
            int irow = i0 + w * 16 + g;
#pragma unroll
            for (int nt = 0; nt < 8; nt++) {
                int col = nt * 8 + 2 * t;
                float* dst = (nt < 4) ? g_ps[ks] : g_pc[ks];
                int cb = col & 31;
                dst[(size_t)cb * NN + irow]           = acc[nt][0];
                dst[(size_t)(cb + 1) * NN + irow]     = acc[nt][1];
                dst[(size_t)cb * NN + irow + 8]       = acc[nt][2];
                dst[(size_t)(cb + 1) * NN + irow + 8] = acc[nt][3];
            }
        }
        gbar(bid);

        // update phase: reduce split-K partials, integrate (theta in regs)
        float ss0 = 0.f, ss1 = 0.f, cs0 = 0.f, cs1 = 0.f;
#pragma unroll
        for (int kq = 0; kq < KSPLIT; kq++) {
            float2 p = *(const float2*)&g_ps[kq][eidx];
            ss0 += p.x; ss1 += p.y;
            float2 q = *(const float2*)&g_pc[kq][eidx];
            cs0 += q.x; cs1 += q.y;
        }
        th0 = fmaf(0.1f, om0 + coef * (ci0 * ss0 - si0 * cs0), th0);
        th1 = fmaf(0.1f, om1 + coef * (ci1 * ss1 - si1 * cs1), th1);

        if (step < NSTEPS - 1) {
            __sincosf(th0, &s0, &c0);   // bf16 rounding dominates intrinsic err
            __sincosf(th1, &s1, &c1);
            sb2 = __floats2bfloat162_rn(s0, s1);
            cb2 = __floats2bfloat162_rn(c0, c1);
            *(__nv_bfloat162*)&g_SCb[eidx]           = sb2;
            *(__nv_bfloat162*)&g_SCb[32 * NN + eidx] = cb2;
            si0 = __low2float(sb2); si1 = __high2float(sb2);
            ci0 = __low2float(cb2); ci1 = __high2float(cb2);
            gbar(bid);
        }
    }

    // ---- epilogue: reference-exact wrap (once), output, coherence ----
    float sn0, cn0, sn1, cn1;
    sincosf(th0, &sn0, &cn0); th0 = atan2f(sn0, cn0);
    sincosf(th1, &sn1, &cn1); th1 = atan2f(sn1, cn1);
    th_out[eidx]     = th0;
    th_out[eidx + 1] = th1;

    if (coh_out) {
        sincosf(th0, &sn0, &cn0);       // trig of wrapped theta (as reference)
        sincosf(th1, &sn1, &cn1);
        float ssP = sn0 + sn1, ccP = cn0 + cn1;
        float* rs = (float*)smem_raw;   // reuse smem as reduce scratch
        float* rc = rs + THREADS;
        __syncthreads();
        rs[tid] = ssP; rc[tid] = ccP;
        __syncthreads();
        for (int o = 128; o > 0; o >>= 1) {
            if (tid < o) { rs[tid] += rs[tid + o]; rc[tid] += rc[tid + o]; }
            __syncthreads();
        }
        if (tid == 0) g_cohP[bid] = make_float2(rs[0], rc[0]);
        gbar(bid);
        if (bid < BB && tid == 0) {
            float ss = 0.f, cc = 0.f;
#pragma unroll
            for (int q = 0; q < 4; q++) {        // batch b spans CTAs 4b..4b+3
                float2 p = g_cohP[bid * 4 + q];
                ss += p.x; cc += p.y;
            }
            float sm = ss * (1.0f / NN), cm = cc * (1.0f / NN);
            coh_out[bid] = sqrtf(cm * cm + sm * sm);
        }
    }
}

extern "C" void kernel_launch(void* const* d_in, const int* in_sizes, int n_in,
                              void* d_out, int out_size) {
    const float* theta = (const float*)d_in[0];
    const float* K     = (const float*)d_in[1];
    const float* omega = (const float*)d_in[2];
    const float* Kg    = (const float*)d_in[3];
    const float* mu    = (const float*)d_in[4];
    float* out = (float*)d_out;

    float* th_buf;
    float* coh_out = nullptr;
    if (out_size >= BB * NN) {
        th_buf = out;
        if (out_size >= BB * NN + BB) coh_out = out + BB * NN;
    } else {
        float* sym;
        cudaGetSymbolAddress((void**)&sym, g_theta_fallback);
        th_buf = sym;
        coh_out = out;
    }

    cudaFuncSetAttribute(k_all, cudaFuncAttributeMaxDynamicSharedMemorySize,
                         SMEM_BYTES);
    k_all<<<CTAS, THREADS, SMEM_BYTES>>>(theta, K, omega, Kg, mu,
                                         th_buf, coh_out);
}

// round 7
// speedup vs baseline: 1.2877x; 1.2877x over previous
#include <cuda_runtime.h>
#include <cuda_bf16.h>
#include <math.h>

#define NN 2048
#define BB 32
#define NSTEPS 10
#define KSPLIT 8
#define KC 256                // K chunk per CTA
#define MT 128                // rows per CTA (MMA tile)
#define CTAS 128
#define THREADS 256
#define SSTR 264              // smem row stride (bf16 elems)
#define SA_ELEMS (MT * SSTR)
#define SB_ELEMS (64 * SSTR)
#define SMEM_BYTES ((SA_ELEMS + SB_ELEMS) * 2)

// Persistent scratch (no allocations allowed)
__device__ __align__(16) __nv_bfloat16 g_SCb[3][64 * NN];  // triple-buffered sin/cos
__device__ __align__(16) float g_ps[2][KSPLIT][BB * NN];   // double-buffered partials
__device__ __align__(16) float g_pc[2][KSPLIT][BB * NN];
__device__ __align__(16) float2 g_cohP[CTAS * BB];
__device__ __align__(16) float g_theta_fallback[BB * NN];
// flags: one 128B line per row-group, 8 x u32 flags within
__device__ __align__(128) unsigned g_flagP[16 * 32];       // [ib*32 + ks]: MMA/partials done
__device__ __align__(128) unsigned g_flagU[16 * 32];       // [ib*32 + ks]: update/g_SCb done
// global barrier (prologue/epilogue only)
__device__ __align__(128) unsigned g_cnt;
__device__ __align__(128) unsigned g_gen;

static __device__ __forceinline__ void cp16(void* dst_smem, const void* src) {
    unsigned d = (unsigned)__cvta_generic_to_shared(dst_smem);
    asm volatile("cp.async.cg.shared.global [%0], [%1], 16;\n" :: "r"(d), "l"(src));
}
static __device__ __forceinline__ void cp_commit() {
    asm volatile("cp.async.commit_group;\n");
}
static __device__ __forceinline__ void cp_wait0() {
    asm volatile("cp.async.wait_group 0;\n");
}

// Full-grid barrier (2 uses total). Sense-reversing, monotonic generation.
static __device__ __forceinline__ void gbar() {
    __syncthreads();
    if (threadIdx.x == 0) {
        unsigned my;
        asm volatile("ld.acquire.gpu.global.u32 %0, [%1];"
                     : "=r"(my) : "l"(&g_gen) : "memory");
        __threadfence();
        unsigned arr = atomicAdd(&g_cnt, 1u);
        if (arr == CTAS - 1) {
            g_cnt = 0;
            asm volatile("red.release.gpu.global.add.u32 [%0], %1;"
                         :: "l"(&g_gen), "r"(1u) : "memory");
        } else {
            unsigned v;
            do {
                __nanosleep(64);
                asm volatile("ld.acquire.gpu.global.u32 %0, [%1];"
                             : "=r"(v) : "l"(&g_gen) : "memory");
            } while (v == my);
        }
        __threadfence();
    }
    __syncthreads();
}

// Warp-0-collective flag poll: lanes with `need` poll *addr until >= target.
static __device__ __forceinline__ void poll_ge(const unsigned* addr,
                                               unsigned target, bool need) {
    for (;;) {
        unsigned x = target;
        if (need)
            asm volatile("ld.acquire.gpu.global.u32 %0, [%1];"
                         : "=r"(x) : "l"(addr) : "memory");
        if (__all_sync(0xffffffffu, x >= target)) break;
        __nanosleep(20);
    }
}

// Signal: all CTA stores -> fence -> bar -> single release-increment.
static __device__ __forceinline__ void signal(unsigned* flag, int tid) {
    __threadfence();
    __syncthreads();
    if (tid == 0)
        asm volatile("red.release.gpu.global.add.u32 [%0], %1;"
                     :: "l"(flag), "r"(1u) : "memory");
}

__global__ void __launch_bounds__(THREADS, 1)
k_all(const float* __restrict__ theta_in, const float* __restrict__ K,
      const float* __restrict__ omega, const float* __restrict__ Kg,
      const float* __restrict__ mu, float* __restrict__ th_out,
      float* __restrict__ coh_out) {
    extern __shared__ __align__(16) char smem_raw[];
    __nv_bfloat16* sA = (__nv_bfloat16*)smem_raw;        // resident K tile
    __nv_bfloat16* sB = sA + SA_ELEMS;                   // per-step sin/cos tile

    int tid  = threadIdx.x;
    int lane = tid & 31;
    int w    = tid >> 5;
    int bid  = blockIdx.x;
    int ib   = bid >> 3, ks = bid & 7;
    int i0   = ib * MT, k0 = ks * KC;
    int g    = lane >> 2, t4 = lane & 3;

    // update-slice mapping: this CTA updates rows [i0 + 16*ks, +16) x 32 batches
    int bb   = tid >> 3;                       // batch 0..31
    int irow = i0 + ks * 16 + (tid & 7) * 2;   // 2 consecutive rows
    int eidx = bb * NN + irow;

    // ---- prologue: reset flags, convert K tile, seed state ----
    if (tid == 0) {
        g_flagP[ib * 32 + ks] = 0u;
        g_flagU[ib * 32 + ks] = 0u;
    }
    {
        const float* Kt = K + (size_t)i0 * NN + k0;
#pragma unroll 4
        for (int it = 0; it < 32; it++) {
            int idx = it * THREADS + tid;           // 8192 float4
            int row = idx >> 6, c = idx & 63;
            float4 v = *(const float4*)(Kt + (size_t)row * NN + c * 4);
            __nv_bfloat162 lo = __floats2bfloat162_rn(v.x, v.y);
            __nv_bfloat162 hi = __floats2bfloat162_rn(v.z, v.w);
            uint2 pk = make_uint2(*(unsigned*)&lo, *(unsigned*)&hi);
            *(uint2*)(sA + row * SSTR + c * 4) = pk;
        }
    }
    float th0 = theta_in[eidx], th1 = theta_in[eidx + 1];
    float om0 = omega[irow],    om1 = omega[irow + 1];
    float coef = (Kg[0] * (1.0f / NN)) * (mu[0] * 0.5f);
    float s0, c0, s1, c1;
    sincosf(th0, &s0, &c0);    // one-time accurate seed
    sincosf(th1, &s1, &c1);
    __nv_bfloat162 sb2 = __floats2bfloat162_rn(s0, s1);
    __nv_bfloat162 cb2 = __floats2bfloat162_rn(c0, c1);
    *(__nv_bfloat162*)&g_SCb[0][eidx]           = sb2;
    *(__nv_bfloat162*)&g_SCb[0][32 * NN + eidx] = cb2;
    float si0 = __low2float(sb2), si1 = __high2float(sb2);
    float ci0 = __low2float(cb2), ci1 = __high2float(cb2);

    gbar();

    // ---- 10 steps ----
    for (int step = 0; step < NSTEPS; step++) {
        int par  = step & 1;        // partials parity
        int par3 = step % 3;        // g_SCb read buffer

        // wait for producers of our B columns (16 CTAs: groups 2ks, 2ks+1)
        if (w == 0) {
            const unsigned* a =
                &g_flagU[(2 * ks + (lane >> 3)) * 32 + (lane & 7)];
            poll_ge(a, (unsigned)step, lane < 16);   // step 0: trivially true
        }
        __syncthreads();

        // fill B tile: 64 rows x 256 bf16 from g_SCb[par3]
        const __nv_bfloat16* Bsrc = g_SCb[par3];
#pragma unroll
        for (int it = 0; it < 8; it++) {
            int idx = it * THREADS + tid;            // 2048 x 16B
            int row = idx >> 5, c = idx & 31;
            cp16(sB + row * SSTR + c * 8,
                 Bsrc + (size_t)row * NN + k0 + c * 8);
        }
        cp_commit();
        cp_wait0();
        __syncthreads();

        float acc[8][4];
#pragma unroll
        for (int nt = 0; nt < 8; nt++)
#pragma unroll
            for (int r = 0; r < 4; r++) acc[nt][r] = 0.f;

#pragma unroll 4
        for (int kk = 0; kk < KC; kk += 16) {
            unsigned a0, a1, a2, a3;
            const __nv_bfloat16* ap =
                sA + (w * 16 + (lane & 15)) * SSTR + kk + ((lane >> 4) * 8);
            unsigned sa = (unsigned)__cvta_generic_to_shared(ap);
            asm volatile(
                "ldmatrix.sync.aligned.m8n8.x4.shared.b16 {%0,%1,%2,%3}, [%4];"
                : "=r"(a0), "=r"(a1), "=r"(a2), "=r"(a3) : "r"(sa));
#pragma unroll
            for (int nt = 0; nt < 8; nt++) {
                const __nv_bfloat16* p = sB + (nt * 8 + g) * SSTR + kk + 2 * t4;
                unsigned b0 = *(const unsigned*)p;
                unsigned b1 = *(const unsigned*)(p + 8);
                asm volatile(
                    "mma.sync.aligned.m16n8k16.row.col.f32.bf16.bf16.f32 "
                    "{%0,%1,%2,%3}, {%4,%5,%6,%7}, {%8,%9}, {%0,%1,%2,%3};"
                    : "+f"(acc[nt][0]), "+f"(acc[nt][1]),
                      "+f"(acc[nt][2]), "+f"(acc[nt][3])
                    : "r"(a0), "r"(a1), "r"(a2), "r"(a3), "r"(b0), "r"(b1));
            }
        }

        // store partials (cols 0-31 sin, 32-63 cos) to parity buffer
        {
            int ir = i0 + w * 16 + g;
#pragma unroll
            for (int nt = 0; nt < 8; nt++) {
                int col = nt * 8 + 2 * t4;
                float* dst = (nt < 4) ? g_ps[par][ks] : g_pc[par][ks];
                int cb = col & 31;
                dst[(size_t)cb * NN + ir]           = acc[nt][0];
                dst[(size_t)(cb + 1) * NN + ir]     = acc[nt][1];
                dst[(size_t)cb * NN + ir + 8]       = acc[nt][2];
                dst[(size_t)(cb + 1) * NN + ir + 8] = acc[nt][3];
            }
        }
        signal(&g_flagP[ib * 32 + ks], tid);     // -> step+1

        // wait for the 8 partial producers of our row slice (group ib)
        if (w == 0) {
            const unsigned* a = &g_flagP[ib * 32 + (lane & 7)];
            poll_ge(a, (unsigned)(step + 1), lane < 8);
        }
        __syncthreads();

        // update: reduce split-K partials, integrate
        float ss0 = 0.f, ss1 = 0.f, cs0 = 0.f, cs1 = 0.f;
#pragma unroll
        for (int kq = 0; kq < KSPLIT; kq++) {
            float2 p = *(const float2*)&g_ps[par][kq][eidx];
            ss0 += p.x; ss1 += p.y;
            float2 q = *(const float2*)&g_pc[par][kq][eidx];
            cs0 += q.x; cs1 += q.y;
        }
        th0 = fmaf(0.1f, om0 + coef * (ci0 * ss0 - si0 * cs0), th0);
        th1 = fmaf(0.1f, om1 + coef * (ci1 * ss1 - si1 * cs1), th1);

        if (step < NSTEPS - 1) {
            int wpar = (step + 1) % 3;
            __sincosf(th0, &s0, &c0);   // bf16 rounding dominates intrinsic err
            __sincosf(th1, &s1, &c1);
            sb2 = __floats2bfloat162_rn(s0, s1);
            cb2 = __floats2bfloat162_rn(c0, c1);
            *(__nv_bfloat162*)&g_SCb[wpar][eidx]           = sb2;
            *(__nv_bfloat162*)&g_SCb[wpar][32 * NN + eidx] = cb2;
            si0 = __low2float(sb2); si1 = __high2float(sb2);
            ci0 = __low2float(cb2); ci1 = __high2float(cb2);
            signal(&g_flagU[ib * 32 + ks], tid);  // -> step+1
        }
    }

    // ---- epilogue: reference-exact wrap (once), output, coherence ----
    float sn0, cn0, sn1, cn1;
    sincosf(th0, &sn0, &cn0); th0 = atan2f(sn0, cn0);
    sincosf(th1, &sn1, &cn1); th1 = atan2f(sn1, cn1);
    th_out[eidx]     = th0;
    th_out[eidx + 1] = th1;

    if (coh_out) {
        sincosf(th0, &sn0, &cn0);       // trig of wrapped theta (as reference)
        sincosf(th1, &sn1, &cn1);
        float ssP = sn0 + sn1, ccP = cn0 + cn1;
        // reduce within 8-lane groups (same batch)
#pragma unroll
        for (int o = 4; o > 0; o >>= 1) {
            ssP += __shfl_xor_sync(0xffffffffu, ssP, o);
            ccP += __shfl_xor_sync(0xffffffffu, ccP, o);
        }
        if ((lane & 7) == 0)
            g_cohP[bid * BB + bb] = make_float2(ssP, ccP);
        gbar();
        if (bid < BB) {       // CTA b reduces batch b over 128 CTA partials
            float* rs = (float*)smem_raw;
            float* rc = rs + THREADS;
            float ss = 0.f, cc = 0.f;
            if (tid < CTAS) {
                float2 p = g_cohP[tid * BB + bid];
                ss = p.x; cc = p.y;
            }
            rs[tid] = ss; rc[tid] = cc;
            __syncthreads();
            for (int o = 128; o > 0; o >>= 1) {
                if (tid < o) { rs[tid] += rs[tid + o]; rc[tid] += rc[tid + o]; }
                __syncthreads();
            }
            if (tid == 0) {
                float sm = rs[0] * (1.0f / NN), cm = rc[0] * (1.0f / NN);
                coh_out[bid] = sqrtf(cm * cm + sm * sm);
            }
        }
    }
}

extern "C" void kernel_launch(void* const* d_in, const int* in_sizes, int n_in,
                              void* d_out, int out_size) {
    const float* theta = (const float*)d_in[0];
    const float* K     = (const float*)d_in[1];
    const float* omega = (const float*)d_in[2];
    const float* Kg    = (const float*)d_in[3];
    const float* mu    = (const float*)d_in[4];
    float* out = (float*)d_out;

    float* th_buf;
    float* coh_out = nullptr;
    if (out_size >= BB * NN) {
        th_buf = out;
        if (out_size >= BB * NN + BB) coh_out = out + BB * NN;
    } else {
        float* sym;
        cudaGetSymbolAddress((void**)&sym, g_theta_fallback);
        th_buf = sym;
        coh_out = out;
    }

    cudaFuncSetAttribute(k_all, cudaFuncAttributeMaxDynamicSharedMemorySize,
                         SMEM_BYTES);
    k_all<<<CTAS, THREADS, SMEM_BYTES>>>(theta, K, omega, Kg, mu,
                                         th_buf, coh_out);
}